// round 13
// baseline (speedup 1.0000x reference)
#include <cuda_runtime.h>

#define BB 4
#define NN 2048
#define NT 50
#define ND 4
#define ITILE 128
#define JTILE 256
#define NJT (NN / JTILE)   /* 8  */
#define NIT (NN / ITILE)   /* 16 */
#define APAD 51            /* padded row stride in float4 units (odd -> spreads f4 banks) */

// ---------------- device scratch (static: allocation-free) ----------------
__device__ float  g_mhat[NT];
__device__ float  g_omega[ND];
__device__ float  g_A[NT * NT * ND];     // softplus(alpha) [ti][tj][d], f4-friendly
__device__ float  g_Acol[NT * ND];       // sum_u A[u][k][d]
__device__ float  g_summhat;
__device__ float4 g_Ep[BB * NN];         // exp(+omega_d * t_j)
__device__ float4 g_EmW[BB * NN];        // omega_d * exp(-omega_d * t_i)
__device__ float  g_mu_i[BB * NN];       // mhat[type_i]
__device__ float  g_comp_i[BB * NN];     // per-event compensator term (masked)
__device__ float  g_partial[NJT][BB * NN];

__device__ __forceinline__ float sp(float x) {
    // softplus, numerically matching log1p(exp(x))
    return fmaxf(x, 0.0f) + log1pf(__expf(-fabsf(x)));
}

// ---------------- kernel 1: parameter transforms ----------------
__global__ void setup_kernel(const float* __restrict__ mu_p,
                             const float* __restrict__ alpha_p,
                             const float* __restrict__ beta_p) {
    int t = threadIdx.x;
    if (t < NT) g_mhat[t] = sp(mu_p[t]);
    if (t < ND) g_omega[t] = sp(beta_p[t]);
    for (int x = t; x < NT * NT * ND; x += blockDim.x) g_A[x] = sp(alpha_p[x]);
    __syncthreads();
    for (int x = t; x < NT * ND; x += blockDim.x) {
        int k = x / ND, d = x - k * ND;
        float s = 0.0f;
        for (int u = 0; u < NT; u++) s += g_A[(u * NT + k) * ND + d];
        g_Acol[x] = s;
    }
    if (t == 0) {
        float s = 0.0f;
        for (int u = 0; u < NT; u++) s += g_mhat[u];
        g_summhat = s;
    }
}

// ---------------- kernel 2: per-event precompute ----------------
__global__ void event_kernel(const float* __restrict__ times,
                             const int*   __restrict__ types,
                             const float* __restrict__ mask,
                             const float* __restrict__ t1) {
    int idx = blockIdx.x * blockDim.x + threadIdx.x;
    if (idx >= BB * NN) return;
    int b = idx / NN;
    float t = times[idx];
    int ty = types[idx];
    float o0 = g_omega[0], o1 = g_omega[1], o2 = g_omega[2], o3 = g_omega[3];
    g_Ep[idx]  = make_float4(__expf(o0 * t), __expf(o1 * t),
                             __expf(o2 * t), __expf(o3 * t));
    g_EmW[idx] = make_float4(o0 * __expf(-o0 * t), o1 * __expf(-o1 * t),
                             o2 * __expf(-o2 * t), o3 * __expf(-o3 * t));
    g_mu_i[idx] = g_mhat[ty];
    float dt1 = t1[b] - t;
    float c = g_Acol[ty * ND + 0] * (1.0f - __expf(-o0 * dt1))
            + g_Acol[ty * ND + 1] * (1.0f - __expf(-o1 * dt1))
            + g_Acol[ty * ND + 2] * (1.0f - __expf(-o2 * dt1))
            + g_Acol[ty * ND + 3] * (1.0f - __expf(-o3 * dt1));
    g_comp_i[idx] = c * mask[idx];
}

// ---------------- kernel 3: triangular pairwise excitation ----------------
__global__ void __launch_bounds__(ITILE) pair_kernel(const int* __restrict__ types) {
    __shared__ float4 A_sh[NT * APAD];
    __shared__ float4 ep_sh[JTILE];
    __shared__ int    ty_sh[JTILE];

    int b  = blockIdx.z;
    int i0 = blockIdx.x * ITILE;
    int j0 = blockIdx.y * JTILE;
    int i  = i0 + threadIdx.x;
    float* part = &g_partial[blockIdx.y][b * NN + i];

    if (j0 >= i0 + ITILE) {   // no j < i intersects this tile
        *part = 0.0f;
        return;
    }

    // cooperative load of A (as float4 per (ti,k)) with padded rows
    const float4* Ag = (const float4*)g_A;
    for (int x = threadIdx.x; x < NT * NT; x += ITILE) {
        int ti = x / NT, k = x - ti * NT;
        A_sh[ti * APAD + k] = Ag[x];
    }
    for (int x = threadIdx.x; x < JTILE; x += ITILE) {
        ep_sh[x] = g_Ep[b * NN + j0 + x];
        ty_sh[x] = types[b * NN + j0 + x];
    }
    __syncthreads();

    int ti = types[b * NN + i];
    const float4* Arow = &A_sh[ti * APAD];
    float ax = 0.f, ay = 0.f, az = 0.f, aw = 0.f;

    int jend = i - j0;                  // strict j < i
    if (jend > JTILE) jend = JTILE;

    #pragma unroll 4
    for (int jj = 0; jj < jend; jj++) {
        float4 a = Arow[ty_sh[jj]];     // per-lane gather (padded rows)
        float4 e = ep_sh[jj];           // warp-uniform broadcast
        ax += a.x * e.x;
        ay += a.y * e.y;
        az += a.z * e.z;
        aw += a.w * e.w;
    }

    float4 w = g_EmW[b * NN + i];
    *part = ax * w.x + ay * w.y + az * w.z + aw * w.w;
}

// ---------------- kernel 4: final reduction per batch ----------------
__global__ void reduce_kernel(const float* __restrict__ mask,
                              const float* __restrict__ t0,
                              const float* __restrict__ t1,
                              float* __restrict__ out) {
    int b = blockIdx.x;
    __shared__ float sll[256], scc[256];
    float ll = 0.f, cc = 0.f;
    for (int i = threadIdx.x; i < NN; i += 256) {
        int idx = b * NN + i;
        float r = g_mu_i[idx];
        #pragma unroll
        for (int jt = 0; jt < NJT; jt++) r += g_partial[jt][idx];
        ll += logf(r + 1e-8f) * mask[idx];
        cc += g_comp_i[idx];
    }
    sll[threadIdx.x] = ll;
    scc[threadIdx.x] = cc;
    __syncthreads();
    for (int s = 128; s > 0; s >>= 1) {
        if (threadIdx.x < s) {
            sll[threadIdx.x] += sll[threadIdx.x + s];
            scc[threadIdx.x] += scc[threadIdx.x + s];
        }
        __syncthreads();
    }
    if (threadIdx.x == 0) {
        out[b]      = sll[0];
        out[BB + b] = (t1[b] - t0[b]) * g_summhat + scc[0];
    }
}

// ---------------- launch ----------------
extern "C" void kernel_launch(void* const* d_in, const int* in_sizes, int n_in,
                              void* d_out, int out_size) {
    const float* times   = (const float*)d_in[0];
    const int*   types   = (const int*)  d_in[1];
    const float* mask    = (const float*)d_in[2];
    const float* t0      = (const float*)d_in[3];
    const float* t1      = (const float*)d_in[4];
    const float* mu_p    = (const float*)d_in[5];
    const float* alpha_p = (const float*)d_in[6];
    const float* beta_p  = (const float*)d_in[7];
    float* out = (float*)d_out;

    setup_kernel<<<1, 256>>>(mu_p, alpha_p, beta_p);
    event_kernel<<<(BB * NN + 255) / 256, 256>>>(times, types, mask, t1);
    dim3 grid(NIT, NJT, BB);
    pair_kernel<<<grid, ITILE>>>(types);
    reduce_kernel<<<BB, 256>>>(mask, t0, t1, out);
}

// round 14
// speedup vs baseline: 1.8240x; 1.8240x over previous
#include <cuda_runtime.h>

#define BB 4
#define NN 2048
#define NT 50
#define ND 4
#define TS 128              /* events per tile */
#define NTL (NN / TS)       /* 16 tiles per batch */
#define APAD 51             /* padded A row stride in float4 units */

// ---------------- device scratch (static: allocation-free) ----------------
__device__ float  g_mhat[NT];
__device__ float  g_omega[ND];
__device__ float  g_A[NT * NT * ND];        // softplus(alpha) [ti][tj][d]
__device__ float  g_Acol[NT * ND];          // sum_u A[u][k][d]
__device__ float  g_summhat;
__device__ float4 g_Ep[BB * NN];            // exp(+omega_d * t_j)
__device__ float4 g_EmW[BB * NN];           // omega_d * exp(-omega_d * t_i)
__device__ float  g_comp[BB * NN];          // per-event compensator term (masked)
__device__ float  g_hist[BB][NTL][NT * ND]; // per-tile type-sums of Ep
__device__ float  g_blk[BB][NTL][2];        // per-block (loglik, comp) partials

__device__ __forceinline__ float sp(float x) {
    return fmaxf(x, 0.0f) + log1pf(__expf(-fabsf(x)));
}

// ---------------- kernel 1: parallel softplus of all params ----------------
__global__ void sp_kernel(const float* __restrict__ mu_p,
                          const float* __restrict__ alpha_p,
                          const float* __restrict__ beta_p) {
    int i = blockIdx.x * blockDim.x + threadIdx.x;
    if (i < NT * NT * ND) {
        g_A[i] = sp(alpha_p[i]);
    } else if (i < NT * NT * ND + NT) {
        int k = i - NT * NT * ND;
        g_mhat[k] = sp(mu_p[k]);
    } else if (i < NT * NT * ND + NT + ND) {
        int k = i - NT * NT * ND - NT;
        g_omega[k] = sp(beta_p[k]);
    }
}

// ---------------- kernel 2: column sums + sum(mhat) ----------------
__global__ void sums_kernel() {
    int tid = threadIdx.x;
    __shared__ float mh[NT];
    if (tid < NT) mh[tid] = g_mhat[tid];
    if (tid < NT * ND) {
        int k = tid >> 2, d = tid & 3;
        float s = 0.0f;
        #pragma unroll 10
        for (int u = 0; u < NT; u++) s += g_A[(u * NT + k) * ND + d];
        g_Acol[tid] = s;
    }
    __syncthreads();
    if (tid == 0) {
        float s = 0.0f;
        for (int u = 0; u < NT; u++) s += mh[u];
        g_summhat = s;
    }
}

// ------- kernel 3: per-event precompute + deterministic tile histograms ----
__global__ void __launch_bounds__(TS) event_hist_kernel(
        const float* __restrict__ times,
        const int*   __restrict__ types,
        const float* __restrict__ mask,
        const float* __restrict__ t1) {
    __shared__ float4 ep_sh[TS];
    __shared__ int    ty_sh[TS];

    int tile = blockIdx.x, b = blockIdx.y, tid = threadIdx.x;
    int idx = b * NN + tile * TS + tid;

    float t  = times[idx];
    int   ty = types[idx];
    float o0 = g_omega[0], o1 = g_omega[1], o2 = g_omega[2], o3 = g_omega[3];

    float4 ep = make_float4(__expf(o0 * t), __expf(o1 * t),
                            __expf(o2 * t), __expf(o3 * t));
    ep_sh[tid] = ep;
    ty_sh[tid] = ty;
    g_Ep[idx]  = ep;
    g_EmW[idx] = make_float4(o0 * __expf(-o0 * t), o1 * __expf(-o1 * t),
                             o2 * __expf(-o2 * t), o3 * __expf(-o3 * t));

    float dt1 = t1[b] - t;
    float c = g_Acol[ty * ND + 0] * (1.0f - __expf(-o0 * dt1))
            + g_Acol[ty * ND + 1] * (1.0f - __expf(-o1 * dt1))
            + g_Acol[ty * ND + 2] * (1.0f - __expf(-o2 * dt1))
            + g_Acol[ty * ND + 3] * (1.0f - __expf(-o3 * dt1));
    g_comp[idx] = c * mask[idx];

    __syncthreads();

    // deterministic histogram: each bin (k,d) scans all 128 events
    const float* epf = (const float*)ep_sh;
    for (int x = tid; x < NT * ND; x += TS) {
        int k = x >> 2, d = x & 3;
        float s = 0.0f;
        #pragma unroll 4
        for (int j = 0; j < TS; j++) {
            s += (ty_sh[j] == k) ? epf[j * 4 + d] : 0.0f;
        }
        g_hist[b][tile][x] = s;
    }
}

// -------- kernel 4: cross-tile (via histogram prefix) + diagonal tile ------
__global__ void __launch_bounds__(TS) main_kernel(
        const int*   __restrict__ types,
        const float* __restrict__ mask) {
    __shared__ float4 A_sh[NT * APAD];   // 40.8 KB
    __shared__ float4 ep_sh[TS];
    __shared__ float4 pre_sh[NT];        // prefix histogram, float4 per type
    __shared__ int    ty_sh[TS];
    __shared__ float  mh_sh[NT];
    __shared__ float  red_ll[TS];
    __shared__ float  red_cc[TS];

    int tile = blockIdx.x, b = blockIdx.y, tid = threadIdx.x;
    int base = b * NN + tile * TS;

    // cooperative load of A with padded rows
    const float4* Ag = (const float4*)g_A;
    for (int x = tid; x < NT * NT; x += TS) {
        int ti = x / NT, k = x - ti * NT;
        A_sh[ti * APAD + k] = Ag[x];
    }
    ep_sh[tid] = g_Ep[base + tid];
    ty_sh[tid] = types[base + tid];
    if (tid < NT) mh_sh[tid] = g_mhat[tid];

    // exclusive prefix of tile histograms (sum of all strictly-lower tiles)
    float* pf = (float*)pre_sh;
    for (int x = tid; x < NT * ND; x += TS) {
        float s = 0.0f;
        for (int tp = 0; tp < tile; tp++) s += g_hist[b][tp][x];
        pf[x] = s;
    }
    __syncthreads();

    int ti = ty_sh[tid];
    const float4* Arow = &A_sh[ti * APAD];
    float ax = 0.f, ay = 0.f, az = 0.f, aw = 0.f;

    // cross-tile part: 50 gathers
    #pragma unroll 5
    for (int k = 0; k < NT; k++) {
        float4 a = Arow[k];
        float4 p = pre_sh[k];
        ax += a.x * p.x; ay += a.y * p.y;
        az += a.z * p.z; aw += a.w * p.w;
    }

    // diagonal part: strict j < i within this tile
    int jend = tid;
    #pragma unroll 4
    for (int jj = 0; jj < jend; jj++) {
        float4 a = Arow[ty_sh[jj]];
        float4 e = ep_sh[jj];
        ax += a.x * e.x; ay += a.y * e.y;
        az += a.z * e.z; aw += a.w * e.w;
    }

    float4 w = g_EmW[base + tid];
    float rate = mh_sh[ti] + ax * w.x + ay * w.y + az * w.z + aw * w.w;
    float ll = logf(rate + 1e-8f) * mask[base + tid];
    float cc = g_comp[base + tid];

    red_ll[tid] = ll;
    red_cc[tid] = cc;
    __syncthreads();
    #pragma unroll
    for (int s = TS / 2; s > 0; s >>= 1) {
        if (tid < s) {
            red_ll[tid] += red_ll[tid + s];
            red_cc[tid] += red_cc[tid + s];
        }
        __syncthreads();
    }
    if (tid == 0) {
        g_blk[b][tile][0] = red_ll[0];
        g_blk[b][tile][1] = red_cc[0];
    }
}

// ---------------- kernel 5: final tiny reduction ----------------
__global__ void final_kernel(const float* __restrict__ t0,
                             const float* __restrict__ t1,
                             float* __restrict__ out) {
    int x = threadIdx.x;              // 64 threads: (b, tile) pairs
    int b = x >> 4, t = x & 15;
    float ll = g_blk[b][t][0];
    float cc = g_blk[b][t][1];
    #pragma unroll
    for (int off = 8; off > 0; off >>= 1) {
        ll += __shfl_down_sync(0xFFFFFFFFu, ll, off, 16);
        cc += __shfl_down_sync(0xFFFFFFFFu, cc, off, 16);
    }
    if ((x & 15) == 0) {
        out[b]      = ll;
        out[BB + b] = (t1[b] - t0[b]) * g_summhat + cc;
    }
}

// ---------------- launch ----------------
extern "C" void kernel_launch(void* const* d_in, const int* in_sizes, int n_in,
                              void* d_out, int out_size) {
    const float* times   = (const float*)d_in[0];
    const int*   types   = (const int*)  d_in[1];
    const float* mask    = (const float*)d_in[2];
    const float* t0      = (const float*)d_in[3];
    const float* t1      = (const float*)d_in[4];
    const float* mu_p    = (const float*)d_in[5];
    const float* alpha_p = (const float*)d_in[6];
    const float* beta_p  = (const float*)d_in[7];
    float* out = (float*)d_out;

    int tot = NT * NT * ND + NT + ND;
    sp_kernel<<<(tot + 255) / 256, 256>>>(mu_p, alpha_p, beta_p);
    sums_kernel<<<1, 256>>>();
    dim3 grid(NTL, BB);
    event_hist_kernel<<<grid, TS>>>(times, types, mask, t1);
    main_kernel<<<grid, TS>>>(types, mask);
    final_kernel<<<1, 64>>>(t0, t1, out);
}

// round 17
// speedup vs baseline: 2.1569x; 1.1825x over previous
#include <cuda_runtime.h>

#define BB 4
#define NN 2048
#define NT 50
#define ND 4
#define TS 128              /* events per tile */
#define NTL (NN / TS)       /* 16 tiles per batch */
#define APAD 51             /* padded A row stride in float4 units */
#define SPL 4               /* threads per event in main kernel */
#define MT (TS * SPL)       /* 512 threads in main kernel */

// ---------------- device scratch (static: allocation-free) ----------------
__device__ float  g_mhat[NT];
__device__ float  g_omega[ND];
__device__ float  g_A[NT * NT * ND];        // softplus(alpha) [ti][tj][d]
__device__ float  g_Acol[NT * ND];          // sum_u A[u][k][d]
__device__ float  g_summhat;
__device__ float4 g_Ep[BB * NN];            // exp(+omega_d * t_j)
__device__ float4 g_EmW[BB * NN];           // omega_d * exp(-omega_d * t_i)
__device__ float  g_comp[BB * NN];          // per-event compensator term (masked)
__device__ float  g_hist[BB][NTL][NT * ND]; // per-tile type-sums of Ep
__device__ float  g_blk[BB][NTL][2];        // per-block (loglik, comp) partials

__device__ __forceinline__ float sp(float x) {
    return fmaxf(x, 0.0f) + log1pf(__expf(-fabsf(x)));
}

// ---------------- kernel 1: parallel softplus of all params ----------------
__global__ void sp_kernel(const float* __restrict__ mu_p,
                          const float* __restrict__ alpha_p,
                          const float* __restrict__ beta_p) {
    int i = blockIdx.x * blockDim.x + threadIdx.x;
    if (i < NT * NT * ND) {
        g_A[i] = sp(alpha_p[i]);
    } else if (i < NT * NT * ND + NT) {
        int k = i - NT * NT * ND;
        g_mhat[k] = sp(mu_p[k]);
    } else if (i < NT * NT * ND + NT + ND) {
        int k = i - NT * NT * ND - NT;
        g_omega[k] = sp(beta_p[k]);
    }
}

// ---------------- kernel 2: column sums + sum(mhat) ----------------
__global__ void sums_kernel() {
    int tid = threadIdx.x;
    __shared__ float mh[NT];
    if (tid < NT) mh[tid] = g_mhat[tid];
    if (tid < NT * ND) {
        int k = tid >> 2, d = tid & 3;
        float s = 0.0f;
        #pragma unroll 10
        for (int u = 0; u < NT; u++) s += g_A[(u * NT + k) * ND + d];
        g_Acol[tid] = s;
    }
    __syncthreads();
    if (tid == 0) {
        float s = 0.0f;
        for (int u = 0; u < NT; u++) s += mh[u];
        g_summhat = s;
    }
}

// ------- kernel 3: per-event precompute + deterministic tile histograms ----
// block = 512 threads: tid<128 does per-event work; histogram 200 bins split
// 2-way over 512 threads (tid>>1 in [0,256) covers all bins in ONE pass).
__global__ void __launch_bounds__(512) event_hist_kernel(
        const float* __restrict__ times,
        const int*   __restrict__ types,
        const float* __restrict__ mask,
        const float* __restrict__ t1) {
    __shared__ float4 ep_sh[TS];
    __shared__ int    ty_sh[TS];

    int tile = blockIdx.x, b = blockIdx.y, tid = threadIdx.x;

    float o0 = g_omega[0], o1 = g_omega[1], o2 = g_omega[2], o3 = g_omega[3];

    if (tid < TS) {
        int idx = b * NN + tile * TS + tid;
        float t  = times[idx];
        int   ty = types[idx];
        float4 ep = make_float4(__expf(o0 * t), __expf(o1 * t),
                                __expf(o2 * t), __expf(o3 * t));
        ep_sh[tid] = ep;
        ty_sh[tid] = ty;
        g_Ep[idx]  = ep;
        g_EmW[idx] = make_float4(o0 * __expf(-o0 * t), o1 * __expf(-o1 * t),
                                 o2 * __expf(-o2 * t), o3 * __expf(-o3 * t));
        float dt1 = t1[b] - t;
        float c = g_Acol[ty * ND + 0] * (1.0f - __expf(-o0 * dt1))
                + g_Acol[ty * ND + 1] * (1.0f - __expf(-o1 * dt1))
                + g_Acol[ty * ND + 2] * (1.0f - __expf(-o2 * dt1))
                + g_Acol[ty * ND + 3] * (1.0f - __expf(-o3 * dt1));
        g_comp[idx] = c * mask[idx];
    }
    __syncthreads();

    // deterministic histogram: bin = tid>>1 in [0,256) covers all 200 bins;
    // invalid bins run predicated so control flow stays uniform for shfl.
    const float* epf = (const float*)ep_sh;
    int bin   = tid >> 1;
    int h     = tid & 1;
    bool valid = bin < NT * ND;
    int binc  = valid ? bin : 0;
    int k = binc >> 2, d = binc & 3;
    float s = 0.0f;
    #pragma unroll 4
    for (int j = h; j < TS; j += 2) {
        s += (ty_sh[j] == k) ? epf[j * 4 + d] : 0.0f;
    }
    s += __shfl_xor_sync(0xFFFFFFFFu, s, 1);
    if (valid && h == 0) g_hist[b][tile][bin] = s;
}

// -------- kernel 4: cross-tile (via histogram prefix) + diagonal tile ------
// 512 threads: 4 threads per event (h = tid&3), shuffle-combined.
__global__ void __launch_bounds__(MT) main_kernel(
        const int*   __restrict__ types,
        const float* __restrict__ mask) {
    __shared__ float4 A_sh[NT * APAD];   // 40.8 KB
    __shared__ float4 ep_sh[TS];
    __shared__ float4 pre_sh[NT];        // prefix histogram, float4 per type
    __shared__ int    ty_sh[TS];
    __shared__ float  mh_sh[NT];
    __shared__ float  red_ll[MT / 32];
    __shared__ float  red_cc[MT / 32];

    int tile = blockIdx.x, b = blockIdx.y, tid = threadIdx.x;
    int base = b * NN + tile * TS;
    int e = tid >> 2, h = tid & 3;

    // cooperative load of A with padded rows
    const float4* Ag = (const float4*)g_A;
    for (int x = tid; x < NT * NT; x += MT) {
        int ti = x / NT, k = x - ti * NT;
        A_sh[ti * APAD + k] = Ag[x];
    }
    if (tid < TS) {
        ep_sh[tid] = g_Ep[base + tid];
        ty_sh[tid] = types[base + tid];
    }
    if (tid < NT) mh_sh[tid] = g_mhat[tid];

    // exclusive prefix of tile histograms (sum of all strictly-lower tiles)
    float* pf = (float*)pre_sh;
    if (tid < NT * ND) {
        float s = 0.0f;
        for (int tp = 0; tp < tile; tp++) s += g_hist[b][tp][tid];
        pf[tid] = s;
    }
    __syncthreads();

    int ti = ty_sh[e];
    const float4* Arow = &A_sh[ti * APAD];
    float ax = 0.f, ay = 0.f, az = 0.f, aw = 0.f;

    // cross-tile part: 50 gathers split 4 ways
    #pragma unroll 4
    for (int k = h; k < NT; k += SPL) {
        float4 a = Arow[k];
        float4 p = pre_sh[k];
        ax += a.x * p.x; ay += a.y * p.y;
        az += a.z * p.z; aw += a.w * p.w;
    }

    // diagonal part: strict j < e within this tile, split 4 ways
    int jend = e;
    #pragma unroll 4
    for (int jj = h; jj < jend; jj += SPL) {
        float4 a = Arow[ty_sh[jj]];
        float4 e4 = ep_sh[jj];
        ax += a.x * e4.x; ay += a.y * e4.y;
        az += a.z * e4.z; aw += a.w * e4.w;
    }

    float4 w = g_EmW[base + e];
    float s = ax * w.x + ay * w.y + az * w.z + aw * w.w;
    // combine the 4 sub-thread partials (lanes 4e..4e+3 are contiguous)
    s += __shfl_xor_sync(0xFFFFFFFFu, s, 1);
    s += __shfl_xor_sync(0xFFFFFFFFu, s, 2);

    float ll = 0.f, cc = 0.f;
    if (h == 0) {
        float rate = mh_sh[ti] + s;
        ll = logf(rate + 1e-8f) * mask[base + e];
        cc = g_comp[base + e];
    }
    // warp reduce (h!=0 lanes carry 0)
    #pragma unroll
    for (int off = 16; off > 0; off >>= 1) {
        ll += __shfl_xor_sync(0xFFFFFFFFu, ll, off);
        cc += __shfl_xor_sync(0xFFFFFFFFu, cc, off);
    }
    int wid = tid >> 5, lane = tid & 31;
    if (lane == 0) { red_ll[wid] = ll; red_cc[wid] = cc; }
    __syncthreads();
    if (tid < 32) {
        float l2 = (tid < MT / 32) ? red_ll[tid] : 0.f;
        float c2 = (tid < MT / 32) ? red_cc[tid] : 0.f;
        #pragma unroll
        for (int off = 8; off > 0; off >>= 1) {
            l2 += __shfl_xor_sync(0xFFFFFFFFu, l2, off);
            c2 += __shfl_xor_sync(0xFFFFFFFFu, c2, off);
        }
        if (tid == 0) {
            g_blk[b][tile][0] = l2;
            g_blk[b][tile][1] = c2;
        }
    }
}

// ---------------- kernel 5: final tiny reduction ----------------
__global__ void final_kernel(const float* __restrict__ t0,
                             const float* __restrict__ t1,
                             float* __restrict__ out) {
    int x = threadIdx.x;              // 64 threads: (b, tile) pairs
    int b = x >> 4;
    float ll = g_blk[b][x & 15][0];
    float cc = g_blk[b][x & 15][1];
    #pragma unroll
    for (int off = 8; off > 0; off >>= 1) {
        ll += __shfl_down_sync(0xFFFFFFFFu, ll, off, 16);
        cc += __shfl_down_sync(0xFFFFFFFFu, cc, off, 16);
    }
    if ((x & 15) == 0) {
        out[b]      = ll;
        out[BB + b] = (t1[b] - t0[b]) * g_summhat + cc;
    }
}

// ---------------- launch ----------------
extern "C" void kernel_launch(void* const* d_in, const int* in_sizes, int n_in,
                              void* d_out, int out_size) {
    const float* times   = (const float*)d_in[0];
    const int*   types   = (const int*)  d_in[1];
    const float* mask    = (const float*)d_in[2];
    const float* t0      = (const float*)d_in[3];
    const float* t1      = (const float*)d_in[4];
    const float* mu_p    = (const float*)d_in[5];
    const float* alpha_p = (const float*)d_in[6];
    const float* beta_p  = (const float*)d_in[7];
    float* out = (float*)d_out;

    int tot = NT * NT * ND + NT + ND;
    sp_kernel<<<(tot + 255) / 256, 256>>>(mu_p, alpha_p, beta_p);
    sums_kernel<<<1, 256>>>();
    dim3 grid(NTL, BB);
    event_hist_kernel<<<grid, 512>>>(times, types, mask, t1);
    main_kernel<<<grid, MT>>>(types, mask);
    final_kernel<<<1, 64>>>(t0, t1, out);
}